// round 1
// baseline (speedup 1.0000x reference)
#include <cuda_runtime.h>
#include <math.h>

#define BATCH 32
#define LSEQ  256
#define DMODEL 384
#define DIN   768
#define NST   16
#define RLOW  48
#define NLAYER 4
#define NCLS  1000
#define MROWS (BATCH*LSEQ)      // 8192
#define KPATCH 588              // 3*14*14
#define PROJW 80                // R + 2*NST

// ---------------- scratch (device globals; no allocation allowed) ----------
__device__ float g_t   [MROWS*DMODEL];
__device__ float g_xn  [MROWS*DMODEL];
__device__ float g_xz  [MROWS*2*DIN];
__device__ float g_xb  [MROWS*DIN];
__device__ float g_proj[MROWS*PROJW];
__device__ float g_dt  [MROWS*DIN];
__device__ float g_y   [MROWS*DIN];
__device__ float g_pool[BATCH*DMODEL];

__device__ __forceinline__ float softplus_f(float v){
    // stable: max(v,0) + log1p(exp(-|v|))
    return fmaxf(v, 0.f) + log1pf(expf(-fabsf(v)));
}
__device__ __forceinline__ float silu_f(float v){
    return v / (1.f + __expf(-v));
}

// ---------------- general tiled GEMM: C[M,N] = A[M,K(lda)] * W[N,K]^T ------
// MODE 0: plain   1: +bias   2: softplus(.+bias)   3: +res (residual add)
template<int MODE>
__global__ void gemm_nt(const float* __restrict__ A, int lda,
                        const float* __restrict__ W,
                        float* __restrict__ C,
                        int M, int N, int Kd,
                        const float* __restrict__ bias,
                        const float* __restrict__ res)
{
    constexpr int BM=128, BN=128, BK=8;
    __shared__ __align__(16) float As[BK][BM];
    __shared__ __align__(16) float Ws[BK][BN];
    const int bm = blockIdx.y * BM;
    const int bn = blockIdx.x * BN;
    const int tid = threadIdx.x;          // 256 threads
    const int tx = tid & 15, ty = tid >> 4;

    float acc[8][8];
    #pragma unroll
    for (int i=0;i<8;i++)
        #pragma unroll
        for (int j=0;j<8;j++) acc[i][j]=0.f;

    for (int k0=0; k0<Kd; k0+=BK){
        #pragma unroll
        for (int i=0;i<4;i++){
            int e = tid + i*256;
            int r = e >> 3, c = e & 7;
            int gm = bm + r, gk = k0 + c;
            As[c][r] = (gm < M && gk < Kd) ? A[(size_t)gm*lda + gk] : 0.f;
        }
        #pragma unroll
        for (int i=0;i<4;i++){
            int e = tid + i*256;
            int r = e >> 3, c = e & 7;
            int gn = bn + r, gk = k0 + c;
            Ws[c][r] = (gn < N && gk < Kd) ? W[(size_t)gn*Kd + gk] : 0.f;
        }
        __syncthreads();
        #pragma unroll
        for (int kk=0; kk<BK; kk++){
            float4 a0 = *(const float4*)&As[kk][ty*8];
            float4 a1 = *(const float4*)&As[kk][ty*8+4];
            float4 w0 = *(const float4*)&Ws[kk][tx*8];
            float4 w1 = *(const float4*)&Ws[kk][tx*8+4];
            float a[8] = {a0.x,a0.y,a0.z,a0.w,a1.x,a1.y,a1.z,a1.w};
            float w[8] = {w0.x,w0.y,w0.z,w0.w,w1.x,w1.y,w1.z,w1.w};
            #pragma unroll
            for (int i=0;i<8;i++)
                #pragma unroll
                for (int j=0;j<8;j++)
                    acc[i][j] = fmaf(a[i], w[j], acc[i][j]);
        }
        __syncthreads();
    }

    #pragma unroll
    for (int i=0;i<8;i++){
        int gm = bm + ty*8 + i;
        if (gm >= M) continue;
        #pragma unroll
        for (int j=0;j<8;j++){
            int gn = bn + tx*8 + j;
            if (gn >= N) continue;
            float v = acc[i][j];
            if (MODE==1 || MODE==2) v += bias[gn];
            if (MODE==2) v = softplus_f(v);
            if (MODE==3) v += res[(size_t)gm*N + gn];
            C[(size_t)gm*N + gn] = v;
        }
    }
}

// ---------------- patch embed: implicit-im2col GEMM ------------------------
// C[m=b*256+py*16+px, n] = sum_k x_gathered[m,k] * patch_w[n,k] + patch_b[n]
__global__ void patch_gemm(const float* __restrict__ x,
                           const float* __restrict__ W,
                           const float* __restrict__ bias,
                           float* __restrict__ C)
{
    constexpr int BM=128, BN=128, BK=8;
    const int M = MROWS, N = DMODEL, Kd = KPATCH;
    __shared__ __align__(16) float As[BK][BM];
    __shared__ __align__(16) float Ws[BK][BN];
    const int bm = blockIdx.y * BM;
    const int bn = blockIdx.x * BN;
    const int tid = threadIdx.x;
    const int tx = tid & 15, ty = tid >> 4;

    float acc[8][8];
    #pragma unroll
    for (int i=0;i<8;i++)
        #pragma unroll
        for (int j=0;j<8;j++) acc[i][j]=0.f;

    for (int k0=0; k0<Kd; k0+=BK){
        #pragma unroll
        for (int i=0;i<4;i++){
            int e = tid + i*256;
            int r = e >> 3, c = e & 7;
            int gm = bm + r, gk = k0 + c;
            float v = 0.f;
            if (gk < Kd){
                int b  = gm >> 8;
                int l  = gm & 255;
                int py = l >> 4, px = l & 15;
                int cc = gk / 196;
                int rem = gk - cc*196;
                int ky = rem / 14;
                int kx = rem - ky*14;
                v = x[((size_t)(b*3 + cc)*224 + (py*14+ky))*224 + (px*14+kx)];
            }
            As[c][r] = v;
        }
        #pragma unroll
        for (int i=0;i<4;i++){
            int e = tid + i*256;
            int r = e >> 3, c = e & 7;
            int gn = bn + r, gk = k0 + c;
            Ws[c][r] = (gn < N && gk < Kd) ? W[(size_t)gn*Kd + gk] : 0.f;
        }
        __syncthreads();
        #pragma unroll
        for (int kk=0; kk<BK; kk++){
            float4 a0 = *(const float4*)&As[kk][ty*8];
            float4 a1 = *(const float4*)&As[kk][ty*8+4];
            float4 w0 = *(const float4*)&Ws[kk][tx*8];
            float4 w1 = *(const float4*)&Ws[kk][tx*8+4];
            float a[8] = {a0.x,a0.y,a0.z,a0.w,a1.x,a1.y,a1.z,a1.w};
            float w[8] = {w0.x,w0.y,w0.z,w0.w,w1.x,w1.y,w1.z,w1.w};
            #pragma unroll
            for (int i=0;i<8;i++)
                #pragma unroll
                for (int j=0;j<8;j++)
                    acc[i][j] = fmaf(a[i], w[j], acc[i][j]);
        }
        __syncthreads();
    }

    #pragma unroll
    for (int i=0;i<8;i++){
        int gm = bm + ty*8 + i;
        #pragma unroll
        for (int j=0;j<8;j++){
            int gn = bn + tx*8 + j;
            if (gn < N)
                C[(size_t)gm*N + gn] = acc[i][j] + bias[gn];
        }
    }
}

// ---------------- LayerNorm over last dim (width 384), warp per row --------
__global__ void layernorm_k(const float* __restrict__ x,
                            const float* __restrict__ w,
                            const float* __restrict__ b,
                            float* __restrict__ out)
{
    int row  = blockIdx.x*8 + (threadIdx.x >> 5);
    int lane = threadIdx.x & 31;
    const float* xr = x + (size_t)row*DMODEL;
    float v[12]; float s=0.f, sq=0.f;
    #pragma unroll
    for (int i=0;i<12;i++){
        float t = xr[lane + i*32];
        v[i] = t; s += t; sq += t*t;
    }
    #pragma unroll
    for (int o=16;o;o>>=1){
        s  += __shfl_xor_sync(0xffffffffu, s,  o);
        sq += __shfl_xor_sync(0xffffffffu, sq, o);
    }
    float m   = s  * (1.f/DMODEL);
    float var = sq * (1.f/DMODEL) - m*m;
    float r   = rsqrtf(var + 1e-5f);
    float* orow = out + (size_t)row*DMODEL;
    #pragma unroll
    for (int i=0;i<12;i++){
        int c = lane + i*32;
        orow[c] = (v[i]-m)*r*w[c] + b[c];
    }
}

// ---------------- causal depthwise conv1d (K=4) + bias + silu --------------
__global__ void conv_silu_k(const float* __restrict__ xz,
                            const float* __restrict__ cw,
                            const float* __restrict__ cb,
                            float* __restrict__ xb)
{
    int idx = blockIdx.x*blockDim.x + threadIdx.x;
    if (idx >= MROWS*DIN) return;
    int d  = idx % DIN;
    int bl = idx / DIN;
    int l  = bl & 255;
    int b  = bl >> 8;
    float acc = cb[d];
    #pragma unroll
    for (int j=0;j<4;j++){
        int ls = l - 3 + j;
        if (ls >= 0)
            acc = fmaf(xz[(size_t)(b*LSEQ+ls)*(2*DIN) + d], cw[d*4+j], acc);
    }
    xb[idx] = silu_f(acc);
}

// ---------------- selective scan: thread per (b,d,n) -----------------------
// fused: y = (sum_n h*C + x*D) * silu(z)
__global__ void scan_k(const float* __restrict__ dtp,
                       const float* __restrict__ xbp,
                       const float* __restrict__ proj,
                       const float* __restrict__ xz,
                       const float* __restrict__ A_log,
                       const float* __restrict__ Dp,
                       float* __restrict__ y)
{
    int n = threadIdx.x & 15;
    int d = blockIdx.x*16 + (threadIdx.x >> 4);
    int b = blockIdx.y;
    float An = -__expf(A_log[d*NST + n]);
    float Dd = Dp[d];
    float h  = 0.f;
    size_t base = (size_t)b*LSEQ;
    for (int l=0;l<LSEQ;l++){
        size_t row = base + l;
        float dt = dtp[row*DIN + d];
        float xv = xbp[row*DIN + d];
        float Bv = proj[row*PROJW + RLOW + n];
        float Cv = proj[row*PROJW + RLOW + NST + n];
        h = fmaf(h, __expf(dt*An), dt*xv*Bv);
        float p = h*Cv;
        p += __shfl_xor_sync(0xffffffffu, p, 8);
        p += __shfl_xor_sync(0xffffffffu, p, 4);
        p += __shfl_xor_sync(0xffffffffu, p, 2);
        p += __shfl_xor_sync(0xffffffffu, p, 1);
        if (n == 0){
            float z = xz[row*(2*DIN) + DIN + d];
            y[row*DIN + d] = (p + xv*Dd) * silu_f(z);
        }
    }
}

// ---------------- mean-pool over L ------------------------------------------
__global__ void pool_k(const float* __restrict__ ln, float* __restrict__ out)
{
    int b = blockIdx.x;
    int d = threadIdx.x;      // 384
    float s = 0.f;
    for (int l=0;l<LSEQ;l++)
        s += ln[(size_t)(b*LSEQ+l)*DMODEL + d];
    out[b*DMODEL + d] = s * (1.f/LSEQ);
}

// ---------------- classifier head -------------------------------------------
__global__ void classifier_k(const float* __restrict__ pool,
                             const float* __restrict__ w,
                             const float* __restrict__ bias,
                             float* __restrict__ out)
{
    int idx = blockIdx.x*blockDim.x + threadIdx.x;   // n*32 + b
    if (idx >= NCLS*BATCH) return;
    int b = idx & 31;
    int n = idx >> 5;
    const float* pr = pool + b*DMODEL;
    const float* wr = w + (size_t)n*DMODEL;
    float acc = bias[n];
    #pragma unroll 4
    for (int k=0;k<DMODEL;k++)
        acc = fmaf(pr[k], wr[k], acc);
    out[b*NCLS + n] = acc;
}

// ---------------- launch -----------------------------------------------------
extern "C" void kernel_launch(void* const* d_in, const int* in_sizes, int n_in,
                              void* d_out, int out_size)
{
    const float* x         = (const float*)d_in[0];
    const float* patch_w   = (const float*)d_in[1];
    const float* patch_b   = (const float*)d_in[2];
    const float* norm_w    = (const float*)d_in[3];
    const float* norm_b    = (const float*)d_in[4];
    const float* in_proj_w = (const float*)d_in[5];
    const float* conv_w    = (const float*)d_in[6];
    const float* conv_b    = (const float*)d_in[7];
    const float* A_log     = (const float*)d_in[8];
    const float* D_ssm     = (const float*)d_in[9];
    const float* xproj_w   = (const float*)d_in[10];
    const float* dtproj_w  = (const float*)d_in[11];
    const float* dtproj_b  = (const float*)d_in[12];
    const float* out_proj_w= (const float*)d_in[13];
    const float* fnorm_w   = (const float*)d_in[14];
    const float* fnorm_b   = (const float*)d_in[15];
    const float* cls_w     = (const float*)d_in[16];
    const float* cls_b     = (const float*)d_in[17];
    float* out = (float*)d_out;

    float *t, *xn, *xz, *xb, *proj, *dt, *y, *pool;
    cudaGetSymbolAddress((void**)&t,    g_t);
    cudaGetSymbolAddress((void**)&xn,   g_xn);
    cudaGetSymbolAddress((void**)&xz,   g_xz);
    cudaGetSymbolAddress((void**)&xb,   g_xb);
    cudaGetSymbolAddress((void**)&proj, g_proj);
    cudaGetSymbolAddress((void**)&dt,   g_dt);
    cudaGetSymbolAddress((void**)&y,    g_y);
    cudaGetSymbolAddress((void**)&pool, g_pool);

    // patch embed -> t : (8192, 384)
    patch_gemm<<<dim3(3,64), 256>>>(x, patch_w, patch_b, t);

    for (int l=0; l<NLAYER; l++){
        // LN
        layernorm_k<<<1024, 256>>>(t, norm_w + l*DMODEL, norm_b + l*DMODEL, xn);
        // in_proj: (8192,1536) = xn(8192,384) @ W(1536,384)^T
        gemm_nt<0><<<dim3(12,64), 256>>>(xn, DMODEL,
            in_proj_w + (size_t)l*2*DIN*DMODEL, xz,
            MROWS, 2*DIN, DMODEL, nullptr, nullptr);
        // depthwise conv + silu -> xb
        conv_silu_k<<<(MROWS*DIN + 255)/256, 256>>>(xz,
            conv_w + (size_t)l*DIN*4, conv_b + l*DIN, xb);
        // x_proj: (8192,80) = xb(8192,768) @ W(80,768)^T
        gemm_nt<0><<<dim3(1,64), 256>>>(xb, DIN,
            xproj_w + (size_t)l*PROJW*DIN, proj,
            MROWS, PROJW, DIN, nullptr, nullptr);
        // dt_proj + softplus: (8192,768) = proj[:, :48](lda=80) @ W(768,48)^T + b
        gemm_nt<2><<<dim3(6,64), 256>>>(proj, PROJW,
            dtproj_w + (size_t)l*DIN*RLOW, dt,
            MROWS, DIN, RLOW, dtproj_b + l*DIN, nullptr);
        // selective scan (fused +x*D and *silu(z))
        scan_k<<<dim3(48,32), 256>>>(dt, xb, proj, xz,
            A_log + (size_t)l*DIN*NST, D_ssm + l*DIN, y);
        // out_proj + residual: t = y(8192,768) @ W(384,768)^T + t
        gemm_nt<3><<<dim3(3,64), 256>>>(y, DIN,
            out_proj_w + (size_t)l*DMODEL*DIN, t,
            MROWS, DMODEL, DIN, nullptr, t);
    }

    // final LN -> mean over L -> classifier
    layernorm_k<<<1024, 256>>>(t, fnorm_w, fnorm_b, xn);
    pool_k<<<BATCH, DMODEL>>>(xn, pool);
    classifier_k<<<(NCLS*BATCH + 255)/256, 256>>>(pool, cls_w, cls_b, out);
}

// round 3
// speedup vs baseline: 1.4737x; 1.4737x over previous
#include <cuda_runtime.h>
#include <cstdint>
#include <math.h>

#define BATCH 32
#define LSEQ  256
#define DMODEL 384
#define DIN   768
#define NST   16
#define RLOW  48
#define NLAYER 4
#define NCLS  1000
#define MROWS (BATCH*LSEQ)      // 8192
#define KPATCH 588              // 3*14*14
#define PROJW 80                // R + 2*NST

// ---------------- scratch (device globals; no allocation allowed) ----------
__device__ float g_t   [MROWS*DMODEL];
__device__ float g_xn  [MROWS*DMODEL];
__device__ float g_xz  [MROWS*2*DIN];
__device__ float g_xb  [MROWS*DIN];
__device__ float g_proj[MROWS*PROJW];
__device__ float g_dt  [MROWS*DIN];
__device__ float g_y   [MROWS*DIN];
__device__ float g_pool[BATCH*DMODEL];

__device__ __forceinline__ float softplus_f(float v){
    return fmaxf(v, 0.f) + log1pf(expf(-fabsf(v)));
}
__device__ __forceinline__ float silu_f(float v){
    return v / (1.f + __expf(-v));
}

// =================== mma.sync tf32 GEMM (3xTF32 split) ======================
// C[M,N] = A[M,K] * W[N,K]^T,  A row-major (lda), W row-major (stride K).
// CTA tile 128x128, 256 threads = 8 warps in 2(m) x 4(n), warp tile 64x32.
// K-chunk 32 in smem, double buffered. Fragments split hi/lo in registers.

#define KCH   32
#define LDS_T 36                       // 32 + 4 pad: conflict-free LDS & STS
#define ATILE (128*LDS_T)              // floats
#define BUFF  (2*ATILE)                // A tile + B tile, floats
#define SMEM_BYTES (2*BUFF*4)          // double buffered: 73728 B

__device__ __forceinline__ void mma8(float* c, const uint32_t* a, const uint32_t* b){
    asm volatile("mma.sync.aligned.m16n8k8.row.col.f32.tf32.tf32.f32 "
        "{%0,%1,%2,%3}, {%4,%5,%6,%7}, {%8,%9}, {%0,%1,%2,%3};"
        : "+f"(c[0]), "+f"(c[1]), "+f"(c[2]), "+f"(c[3])
        : "r"(a[0]), "r"(a[1]), "r"(a[2]), "r"(a[3]), "r"(b[0]), "r"(b[1]));
}

__device__ __forceinline__ void split2(float v, uint32_t& hi, uint32_t& lo){
    uint32_t h = __float_as_uint(v) & 0xFFFFE000u;
    float l = v - __uint_as_float(h);
    hi = h;
    lo = __float_as_uint(l) & 0xFFFFE000u;
}

// MODE 0: plain  1: += res (same layout as C)  3: softplus(. + bias[n])
template<int MODE>
__global__ void __launch_bounds__(256) mma_gemm(
        const float* __restrict__ A, int lda,
        const float* __restrict__ W, int Nrows,
        float* __restrict__ C, int ldc, int Kd,
        const float* __restrict__ aux)
{
    extern __shared__ float smem[];
    const int tid = threadIdx.x;
    const int wid = tid >> 5, lane = tid & 31;
    const int wm = wid & 1, wn = wid >> 1;
    const int g = lane >> 2, t = lane & 3;
    const int bm = blockIdx.y << 7, bn = blockIdx.x << 7;
    const int NC = (Kd + KCH - 1) / KCH;

    float acc[4][4][4];
    #pragma unroll
    for (int i=0;i<4;i++)
        #pragma unroll
        for (int j=0;j<4;j++)
            #pragma unroll
            for (int q=0;q<4;q++) acc[i][j][q]=0.f;

    float4 regA[4], regB[4];

    auto ldg_chunk = [&](int k0){
        #pragma unroll
        for (int i=0;i<4;i++){
            int e = tid + (i<<8);
            int r = e >> 3, c4 = e & 7;
            int gk = k0 + (c4<<2);
            // A
            {
                float4 v = make_float4(0.f,0.f,0.f,0.f);
                const float* p = A + (size_t)(bm + r)*lda + gk;
                if (gk + 4 <= Kd) v = *(const float4*)p;
                else {
                    float* pv = &v.x;
                    #pragma unroll
                    for (int q=0;q<4;q++) if (gk+q < Kd) pv[q] = p[q];
                }
                regA[i] = v;
            }
            // W
            {
                float4 v = make_float4(0.f,0.f,0.f,0.f);
                int gr = bn + r;
                if (gr < Nrows){
                    const float* p = W + (size_t)gr*Kd + gk;
                    if (gk + 4 <= Kd) v = *(const float4*)p;
                    else {
                        float* pv = &v.x;
                        #pragma unroll
                        for (int q=0;q<4;q++) if (gk+q < Kd) pv[q] = p[q];
                    }
                }
                regB[i] = v;
            }
        }
    };
    auto sts_chunk = [&](float* buf){
        #pragma unroll
        for (int i=0;i<4;i++){
            int e = tid + (i<<8);
            int r = e >> 3, c4 = e & 7;
            *(float4*)&buf[r*LDS_T + (c4<<2)]         = regA[i];
            *(float4*)&buf[ATILE + r*LDS_T + (c4<<2)] = regB[i];
        }
    };

    ldg_chunk(0);
    sts_chunk(smem);
    __syncthreads();

    for (int j=0;j<NC;j++){
        const float* As = smem + (j&1)*BUFF;
        const float* Bs = As + ATILE;
        if (j+1 < NC) ldg_chunk((j+1)*KCH);

        #pragma unroll
        for (int ks=0; ks<4; ks++){
            const int k0 = ks*8;
            uint32_t ah[4][4], al[4][4];
            #pragma unroll
            for (int im=0; im<4; im++){
                int rb = wm*64 + im*16 + g;
                #pragma unroll
                for (int q=0;q<4;q++){
                    int rr = rb + ((q&1)<<3);
                    int kk = k0 + t + ((q>>1)<<2);
                    split2(As[rr*LDS_T + kk], ah[im][q], al[im][q]);
                }
            }
            uint32_t bh[4][2], bl[4][2];
            #pragma unroll
            for (int in_=0; in_<4; in_++){
                int nb = wn*32 + in_*8 + g;
                #pragma unroll
                for (int q=0;q<2;q++){
                    split2(Bs[nb*LDS_T + k0 + t + (q<<2)], bh[in_][q], bl[in_][q]);
                }
            }
            #pragma unroll
            for (int im=0; im<4; im++)
                #pragma unroll
                for (int in_=0; in_<4; in_++){
                    mma8(acc[im][in_], ah[im], bh[in_]);
                    mma8(acc[im][in_], ah[im], bl[in_]);
                    mma8(acc[im][in_], al[im], bh[in_]);
                }
        }

        if (j+1 < NC){
            sts_chunk(smem + ((j+1)&1)*BUFF);
        }
        __syncthreads();
    }

    // epilogue
    #pragma unroll
    for (int im=0; im<4; im++){
        int r0 = bm + wm*64 + im*16 + g;
        #pragma unroll
        for (int in_=0; in_<4; in_++){
            int cc = bn + wn*32 + in_*8 + (t<<1);
            if (cc < Nrows){
                float2 v0 = make_float2(acc[im][in_][0], acc[im][in_][1]);
                float2 v1 = make_float2(acc[im][in_][2], acc[im][in_][3]);
                if (MODE==1){
                    float2 r = *(const float2*)&aux[(size_t)r0*ldc + cc];
                    v0.x += r.x; v0.y += r.y;
                    float2 s = *(const float2*)&aux[(size_t)(r0+8)*ldc + cc];
                    v1.x += s.x; v1.y += s.y;
                } else if (MODE==3){
                    float2 b = *(const float2*)&aux[cc];
                    v0.x = softplus_f(v0.x + b.x); v0.y = softplus_f(v0.y + b.y);
                    v1.x = softplus_f(v1.x + b.x); v1.y = softplus_f(v1.y + b.y);
                }
                *(float2*)&C[(size_t)r0*ldc + cc]     = v0;
                *(float2*)&C[(size_t)(r0+8)*ldc + cc] = v1;
            }
        }
    }
}

// ---------------- patch embed: implicit-im2col mma GEMM + bias --------------
__global__ void __launch_bounds__(256) mma_patch(
        const float* __restrict__ X,
        const float* __restrict__ W,
        const float* __restrict__ bias,
        float* __restrict__ C)
{
    const int Kd = KPATCH, Nrows = DMODEL, ldc = DMODEL;
    extern __shared__ float smem[];
    const int tid = threadIdx.x;
    const int wid = tid >> 5, lane = tid & 31;
    const int wm = wid & 1, wn = wid >> 1;
    const int g = lane >> 2, t = lane & 3;
    const int bm = blockIdx.y << 7, bn = blockIdx.x << 7;
    const int NC = (Kd + KCH - 1) / KCH;  // 19

    float acc[4][4][4];
    #pragma unroll
    for (int i=0;i<4;i++)
        #pragma unroll
        for (int j=0;j<4;j++)
            #pragma unroll
            for (int q=0;q<4;q++) acc[i][j][q]=0.f;

    float4 regA[4], regB[4];

    auto ldg_chunk = [&](int k0){
        #pragma unroll
        for (int i=0;i<4;i++){
            int e = tid + (i<<8);
            int r = e >> 3, c4 = e & 7;
            int gk0 = k0 + (c4<<2);
            // A: gather from image
            {
                int gm = bm + r;
                int b  = gm >> 8, l = gm & 255;
                int py = l >> 4, px = l & 15;
                const float* xb = X + (size_t)b*3*224*224 + (py*14)*224 + px*14;
                float4 v = make_float4(0.f,0.f,0.f,0.f);
                float* pv = &v.x;
                #pragma unroll
                for (int q=0;q<4;q++){
                    int gk = gk0 + q;
                    if (gk < KPATCH){
                        int cc  = gk / 196;
                        int rem = gk - cc*196;
                        int ky  = rem / 14;
                        int kx  = rem - ky*14;
                        pv[q] = xb[(size_t)cc*50176 + ky*224 + kx];
                    }
                }
                regA[i] = v;
            }
            // W
            {
                float4 v = make_float4(0.f,0.f,0.f,0.f);
                int gr = bn + r;
                if (gr < Nrows){
                    const float* p = W + (size_t)gr*Kd + gk0;
                    float* pv = &v.x;
                    if (gk0 + 4 <= Kd) v = *(const float4*)p;
                    else {
                        #pragma unroll
                        for (int q=0;q<4;q++) if (gk0+q < Kd) pv[q] = p[q];
                    }
                }
                regB[i] = v;
            }
        }
    };
    auto sts_chunk = [&](float* buf){
        #pragma unroll
        for (int i=0;i<4;i++){
            int e = tid + (i<<8);
            int r = e >> 3, c4 = e & 7;
            *(float4*)&buf[r*LDS_T + (c4<<2)]         = regA[i];
            *(float4*)&buf[ATILE + r*LDS_T + (c4<<2)] = regB[i];
        }
    };

    ldg_chunk(0);
    sts_chunk(smem);
    __syncthreads();

    for (int j=0;j<NC;j++){
        const float* As = smem + (j&1)*BUFF;
        const float* Bs = As + ATILE;
        if (j+1 < NC) ldg_chunk((j+1)*KCH);

        #pragma unroll
        for (int ks=0; ks<4; ks++){
            const int k0 = ks*8;
            uint32_t ah[4][4], al[4][4];
            #pragma unroll
            for (int im=0; im<4; im++){
                int rb = wm*64 + im*16 + g;
                #pragma unroll
                for (int q=0;q<4;q++){
                    int rr = rb + ((q&1)<<3);
                    int kk = k0 + t + ((q>>1)<<2);
                    split2(As[rr*LDS_T + kk], ah[im][q], al[im][q]);
                }
            }
            uint32_t bh[4][2], bl[4][2];
            #pragma unroll
            for (int in_=0; in_<4; in_++){
                int nb = wn*32 + in_*8 + g;
                #pragma unroll
                for (int q=0;q<2;q++){
                    split2(Bs[nb*LDS_T + k0 + t + (q<<2)], bh[in_][q], bl[in_][q]);
                }
            }
            #pragma unroll
            for (int im=0; im<4; im++)
                #pragma unroll
                for (int in_=0; in_<4; in_++){
                    mma8(acc[im][in_], ah[im], bh[in_]);
                    mma8(acc[im][in_], ah[im], bl[in_]);
                    mma8(acc[im][in_], al[im], bh[in_]);
                }
        }

        if (j+1 < NC){
            sts_chunk(smem + ((j+1)&1)*BUFF);
        }
        __syncthreads();
    }

    #pragma unroll
    for (int im=0; im<4; im++){
        int r0 = bm + wm*64 + im*16 + g;
        #pragma unroll
        for (int in_=0; in_<4; in_++){
            int cc = bn + wn*32 + in_*8 + (t<<1);
            if (cc < Nrows){
                float2 b = *(const float2*)&bias[cc];
                float2 v0 = make_float2(acc[im][in_][0] + b.x, acc[im][in_][1] + b.y);
                float2 v1 = make_float2(acc[im][in_][2] + b.x, acc[im][in_][3] + b.y);
                *(float2*)&C[(size_t)r0*ldc + cc]     = v0;
                *(float2*)&C[(size_t)(r0+8)*ldc + cc] = v1;
            }
        }
    }
}

// ---------------- LayerNorm over last dim (width 384), warp per row --------
__global__ void layernorm_k(const float* __restrict__ x,
                            const float* __restrict__ w,
                            const float* __restrict__ b,
                            float* __restrict__ out)
{
    int row  = blockIdx.x*8 + (threadIdx.x >> 5);
    int lane = threadIdx.x & 31;
    const float* xr = x + (size_t)row*DMODEL;
    float v[12]; float s=0.f, sq=0.f;
    #pragma unroll
    for (int i=0;i<12;i++){
        float t = xr[lane + i*32];
        v[i] = t; s += t; sq += t*t;
    }
    #pragma unroll
    for (int o=16;o;o>>=1){
        s  += __shfl_xor_sync(0xffffffffu, s,  o);
        sq += __shfl_xor_sync(0xffffffffu, sq, o);
    }
    float m   = s  * (1.f/DMODEL);
    float var = sq * (1.f/DMODEL) - m*m;
    float r   = rsqrtf(var + 1e-5f);
    float* orow = out + (size_t)row*DMODEL;
    #pragma unroll
    for (int i=0;i<12;i++){
        int c = lane + i*32;
        orow[c] = (v[i]-m)*r*w[c] + b[c];
    }
}

// ---------------- causal depthwise conv1d (K=4) + bias + silu --------------
__global__ void conv_silu_k(const float* __restrict__ xz,
                            const float* __restrict__ cw,
                            const float* __restrict__ cb,
                            float* __restrict__ xb)
{
    int idx = blockIdx.x*blockDim.x + threadIdx.x;
    if (idx >= MROWS*DIN) return;
    int d  = idx % DIN;
    int bl = idx / DIN;
    int l  = bl & 255;
    int b  = bl >> 8;
    float acc = cb[d];
    #pragma unroll
    for (int j=0;j<4;j++){
        int ls = l - 3 + j;
        if (ls >= 0)
            acc = fmaf(xz[(size_t)(b*LSEQ+ls)*(2*DIN) + d], cw[d*4+j], acc);
    }
    xb[idx] = silu_f(acc);
}

// ---------------- selective scan: thread per (b,d,n) -----------------------
__global__ void scan_k(const float* __restrict__ dtp,
                       const float* __restrict__ xbp,
                       const float* __restrict__ proj,
                       const float* __restrict__ xz,
                       const float* __restrict__ A_log,
                       const float* __restrict__ Dp,
                       float* __restrict__ y)
{
    int n = threadIdx.x & 15;
    int d = blockIdx.x*16 + (threadIdx.x >> 4);
    int b = blockIdx.y;
    float An = -__expf(A_log[d*NST + n]);
    float Dd = Dp[d];
    float h  = 0.f;
    size_t base = (size_t)b*LSEQ;
    for (int l=0;l<LSEQ;l++){
        size_t row = base + l;
        float dt = dtp[row*DIN + d];
        float xv = xbp[row*DIN + d];
        float Bv = proj[row*PROJW + RLOW + n];
        float Cv = proj[row*PROJW + RLOW + NST + n];
        h = fmaf(h, __expf(dt*An), dt*xv*Bv);
        float p = h*Cv;
        p += __shfl_xor_sync(0xffffffffu, p, 8);
        p += __shfl_xor_sync(0xffffffffu, p, 4);
        p += __shfl_xor_sync(0xffffffffu, p, 2);
        p += __shfl_xor_sync(0xffffffffu, p, 1);
        if (n == 0){
            float z = xz[row*(2*DIN) + DIN + d];
            y[row*DIN + d] = (p + xv*Dd) * silu_f(z);
        }
    }
}

// ---------------- mean-pool over L ------------------------------------------
__global__ void pool_k(const float* __restrict__ ln, float* __restrict__ out)
{
    int b = blockIdx.x;
    int d = threadIdx.x;
    float s = 0.f;
    for (int l=0;l<LSEQ;l++)
        s += ln[(size_t)(b*LSEQ+l)*DMODEL + d];
    out[b*DMODEL + d] = s * (1.f/LSEQ);
}

// ---------------- classifier head -------------------------------------------
__global__ void classifier_k(const float* __restrict__ pool,
                             const float* __restrict__ w,
                             const float* __restrict__ bias,
                             float* __restrict__ out)
{
    int idx = blockIdx.x*blockDim.x + threadIdx.x;
    if (idx >= NCLS*BATCH) return;
    int b = idx & 31;
    int n = idx >> 5;
    const float* pr = pool + b*DMODEL;
    const float* wr = w + (size_t)n*DMODEL;
    float acc = bias[n];
    #pragma unroll 4
    for (int k=0;k<DMODEL;k++)
        acc = fmaf(pr[k], wr[k], acc);
    out[b*NCLS + n] = acc;
}

// ---------------- launch -----------------------------------------------------
extern "C" void kernel_launch(void* const* d_in, const int* in_sizes, int n_in,
                              void* d_out, int out_size)
{
    const float* x         = (const float*)d_in[0];
    const float* patch_w   = (const float*)d_in[1];
    const float* patch_b   = (const float*)d_in[2];
    const float* norm_w    = (const float*)d_in[3];
    const float* norm_b    = (const float*)d_in[4];
    const float* in_proj_w = (const float*)d_in[5];
    const float* conv_w    = (const float*)d_in[6];
    const float* conv_b    = (const float*)d_in[7];
    const float* A_log     = (const float*)d_in[8];
    const float* D_ssm     = (const float*)d_in[9];
    const float* xproj_w   = (const float*)d_in[10];
    const float* dtproj_w  = (const float*)d_in[11];
    const float* dtproj_b  = (const float*)d_in[12];
    const float* out_proj_w= (const float*)d_in[13];
    const float* fnorm_w   = (const float*)d_in[14];
    const float* fnorm_b   = (const float*)d_in[15];
    const float* cls_w     = (const float*)d_in[16];
    const float* cls_b     = (const float*)d_in[17];
    float* out = (float*)d_out;

    float *t, *xn, *xz, *xb, *proj, *dt, *y, *pool;
    cudaGetSymbolAddress((void**)&t,    g_t);
    cudaGetSymbolAddress((void**)&xn,   g_xn);
    cudaGetSymbolAddress((void**)&xz,   g_xz);
    cudaGetSymbolAddress((void**)&xb,   g_xb);
    cudaGetSymbolAddress((void**)&proj, g_proj);
    cudaGetSymbolAddress((void**)&dt,   g_dt);
    cudaGetSymbolAddress((void**)&y,    g_y);
    cudaGetSymbolAddress((void**)&pool, g_pool);

    cudaFuncSetAttribute((const void*)mma_patch,   cudaFuncAttributeMaxDynamicSharedMemorySize, SMEM_BYTES);
    cudaFuncSetAttribute((const void*)mma_gemm<0>, cudaFuncAttributeMaxDynamicSharedMemorySize, SMEM_BYTES);
    cudaFuncSetAttribute((const void*)mma_gemm<1>, cudaFuncAttributeMaxDynamicSharedMemorySize, SMEM_BYTES);
    cudaFuncSetAttribute((const void*)mma_gemm<3>, cudaFuncAttributeMaxDynamicSharedMemorySize, SMEM_BYTES);

    // patch embed -> t : (8192, 384)
    mma_patch<<<dim3(3,64), 256, SMEM_BYTES>>>(x, patch_w, patch_b, t);

    for (int l=0; l<NLAYER; l++){
        layernorm_k<<<1024, 256>>>(t, norm_w + l*DMODEL, norm_b + l*DMODEL, xn);
        // in_proj: (8192,1536) = xn(8192,384) @ W(1536,384)^T
        mma_gemm<0><<<dim3(12,64), 256, SMEM_BYTES>>>(xn, DMODEL,
            in_proj_w + (size_t)l*2*DIN*DMODEL, 2*DIN,
            xz, 2*DIN, DMODEL, nullptr);
        conv_silu_k<<<(MROWS*DIN + 255)/256, 256>>>(xz,
            conv_w + (size_t)l*DIN*4, conv_b + l*DIN, xb);
        // x_proj: (8192,80) = xb(8192,768) @ W(80,768)^T
        mma_gemm<0><<<dim3(1,64), 256, SMEM_BYTES>>>(xb, DIN,
            xproj_w + (size_t)l*PROJW*DIN, PROJW,
            proj, PROJW, DIN, nullptr);
        // dt_proj + softplus: (8192,768) = proj[:, :48](lda=80) @ W(768,48)^T + b
        mma_gemm<3><<<dim3(6,64), 256, SMEM_BYTES>>>(proj, PROJW,
            dtproj_w + (size_t)l*DIN*RLOW, DIN,
            dt, DIN, RLOW, dtproj_b + l*DIN);
        scan_k<<<dim3(48,32), 256>>>(dt, xb, proj, xz,
            A_log + (size_t)l*DIN*NST, D_ssm + l*DIN, y);
        // out_proj + residual: t = y(8192,768) @ W(384,768)^T + t
        mma_gemm<1><<<dim3(3,64), 256, SMEM_BYTES>>>(y, DIN,
            out_proj_w + (size_t)l*DMODEL*DIN, DMODEL,
            t, DMODEL, DIN, t);
    }

    layernorm_k<<<1024, 256>>>(t, fnorm_w, fnorm_b, xn);
    pool_k<<<BATCH, DMODEL>>>(xn, pool);
    classifier_k<<<(NCLS*BATCH + 255)/256, 256>>>(pool, cls_w, cls_b, out);
}

// round 4
// speedup vs baseline: 1.6568x; 1.1242x over previous
#include <cuda_runtime.h>
#include <cuda_fp16.h>
#include <cstdint>
#include <math.h>

#define BATCH 32
#define LSEQ  256
#define DMODEL 384
#define DIN   768
#define NST   16
#define RLOW  48
#define NLAYER 4
#define NCLS  1000
#define MROWS (BATCH*LSEQ)      // 8192
#define KPATCH 588              // 3*14*14
#define PROJW 80                // R + 2*NST

// ---------------- scratch (device globals; no allocation allowed) ----------
__device__ float g_t   [MROWS*DMODEL];
__device__ float g_xn  [MROWS*DMODEL];
__device__ float g_xz  [MROWS*2*DIN];
__device__ float g_xb  [MROWS*DIN];
__device__ float g_proj[MROWS*PROJW];
__device__ float g_dt  [MROWS*DIN];
__device__ float g_y   [MROWS*DIN];
__device__ float g_pool[BATCH*DMODEL];

__device__ __forceinline__ float softplus_f(float v){
    return fmaxf(v, 0.f) + log1pf(expf(-fabsf(v)));
}
__device__ __forceinline__ float silu_f(float v){
    return v / (1.f + __expf(-v));
}

// =================== mma.sync fp16-split GEMM ================================
// C[M,N] = A[M,K] * W[N,K]^T. Split each fp32 value v = hi + lo/2048 with
// hi, lo fp16. acc1 += Ah*Bh ; acc2 += Ah*Bl + Al*Bh ; C = acc1 + acc2/2048.
// CTA tile 128x128, 256 threads (8 warps, 2m x 4n), warp tile 64x32.
// K-chunk 32, double-buffered smem (half, row stride 40 -> conflict-free LDS).

#define KCH    32
#define HSTR   40                         // halves per row (32 + 8 pad)
#define SUBT   (128*HSTR)                 // halves per subtile (10240 B)
#define BUFFH  (4*SUBT)                   // Ah, Al, Bh, Bl
#define SMEM_BYTES (2*BUFFH*2)            // 81920 B

__device__ __forceinline__ void mma16(float* c, const uint32_t* a, const uint32_t* b){
    asm volatile("mma.sync.aligned.m16n8k16.row.col.f32.f16.f16.f32 "
        "{%0,%1,%2,%3}, {%4,%5,%6,%7}, {%8,%9}, {%0,%1,%2,%3};"
        : "+f"(c[0]), "+f"(c[1]), "+f"(c[2]), "+f"(c[3])
        : "r"(a[0]), "r"(a[1]), "r"(a[2]), "r"(a[3]), "r"(b[0]), "r"(b[1]));
}

__device__ __forceinline__ void split_h(float v, __half& h, __half& l){
    h = __float2half_rn(v);
    l = __float2half_rn((v - __half2float(h)) * 2048.f);
}
__device__ __forceinline__ void split_store4(__half* hi, __half* lo, int off, float4 v){
    __half h0,h1,h2,h3,l0,l1,l2,l3;
    split_h(v.x,h0,l0); split_h(v.y,h1,l1); split_h(v.z,h2,l2); split_h(v.w,h3,l3);
    __half2 H0 = __halves2half2(h0,h1), H1 = __halves2half2(h2,h3);
    __half2 L0 = __halves2half2(l0,l1), L1 = __halves2half2(l2,l3);
    uint2 uh, ul;
    uh.x = *(uint32_t*)&H0; uh.y = *(uint32_t*)&H1;
    ul.x = *(uint32_t*)&L0; ul.y = *(uint32_t*)&L1;
    *(uint2*)&hi[off] = uh;
    *(uint2*)&lo[off] = ul;
}

// MODE 0: plain  1: += res (same layout as C)  3: softplus(. + bias[n])
template<int MODE>
__global__ void __launch_bounds__(256) mma_gemm(
        const float* __restrict__ A, int lda,
        const float* __restrict__ W, int Nrows,
        float* __restrict__ C, int ldc, int Kd,
        const float* __restrict__ aux)
{
    extern __shared__ __half smem[];
    const int tid = threadIdx.x;
    const int wid = tid >> 5, lane = tid & 31;
    const int wm = wid & 1, wn = wid >> 1;
    const int g = lane >> 2, t = lane & 3;
    const int bm = blockIdx.y << 7, bn = blockIdx.x << 7;
    const int NC = (Kd + KCH - 1) / KCH;

    float acc1[4][4][4], acc2[4][4][4];
    #pragma unroll
    for (int i=0;i<4;i++)
        #pragma unroll
        for (int j=0;j<4;j++)
            #pragma unroll
            for (int q=0;q<4;q++){ acc1[i][j][q]=0.f; acc2[i][j][q]=0.f; }

    float4 regA[4], regB[4];

    auto ldg_chunk = [&](int k0){
        #pragma unroll
        for (int i=0;i<4;i++){
            int e = tid + (i<<8);
            int r = e >> 3, c4 = e & 7;
            int gk = k0 + (c4<<2);
            {
                float4 v = make_float4(0.f,0.f,0.f,0.f);
                const float* p = A + (size_t)(bm + r)*lda + gk;
                if (gk + 4 <= Kd) v = *(const float4*)p;
                else {
                    float* pv = &v.x;
                    #pragma unroll
                    for (int q=0;q<4;q++) if (gk+q < Kd) pv[q] = p[q];
                }
                regA[i] = v;
            }
            {
                float4 v = make_float4(0.f,0.f,0.f,0.f);
                int gr = bn + r;
                if (gr < Nrows){
                    const float* p = W + (size_t)gr*Kd + gk;
                    if (gk + 4 <= Kd) v = *(const float4*)p;
                    else {
                        float* pv = &v.x;
                        #pragma unroll
                        for (int q=0;q<4;q++) if (gk+q < Kd) pv[q] = p[q];
                    }
                }
                regB[i] = v;
            }
        }
    };
    auto sts_chunk = [&](__half* buf){
        #pragma unroll
        for (int i=0;i<4;i++){
            int e = tid + (i<<8);
            int r = e >> 3, c4 = e & 7;
            int off = r*HSTR + (c4<<2);
            split_store4(buf,          buf + SUBT,   off, regA[i]);   // Ah, Al
            split_store4(buf + 2*SUBT, buf + 3*SUBT, off, regB[i]);   // Bh, Bl
        }
    };

    ldg_chunk(0);
    sts_chunk(smem);
    __syncthreads();

    for (int j=0;j<NC;j++){
        const __half* Ah = smem + (j&1)*BUFFH;
        const __half* Al = Ah + SUBT;
        const __half* Bh = Ah + 2*SUBT;
        const __half* Bl = Ah + 3*SUBT;
        if (j+1 < NC) ldg_chunk((j+1)*KCH);

        #pragma unroll
        for (int ks=0; ks<2; ks++){
            const int k0 = ks*16;
            uint32_t ah[4][4], al[4][4];
            #pragma unroll
            for (int im=0; im<4; im++){
                int rb = (wm*64 + im*16 + g)*HSTR + k0 + 2*t;
                ah[im][0] = *(const uint32_t*)&Ah[rb];
                ah[im][1] = *(const uint32_t*)&Ah[rb + 8*HSTR];
                ah[im][2] = *(const uint32_t*)&Ah[rb + 8];
                ah[im][3] = *(const uint32_t*)&Ah[rb + 8*HSTR + 8];
                al[im][0] = *(const uint32_t*)&Al[rb];
                al[im][1] = *(const uint32_t*)&Al[rb + 8*HSTR];
                al[im][2] = *(const uint32_t*)&Al[rb + 8];
                al[im][3] = *(const uint32_t*)&Al[rb + 8*HSTR + 8];
            }
            uint32_t bh[4][2], bl[4][2];
            #pragma unroll
            for (int in_=0; in_<4; in_++){
                int nb = (wn*32 + in_*8 + g)*HSTR + k0 + 2*t;
                bh[in_][0] = *(const uint32_t*)&Bh[nb];
                bh[in_][1] = *(const uint32_t*)&Bh[nb + 8];
                bl[in_][0] = *(const uint32_t*)&Bl[nb];
                bl[in_][1] = *(const uint32_t*)&Bl[nb + 8];
            }
            #pragma unroll
            for (int im=0; im<4; im++)
                #pragma unroll
                for (int in_=0; in_<4; in_++){
                    mma16(acc1[im][in_], ah[im], bh[in_]);
                    mma16(acc2[im][in_], ah[im], bl[in_]);
                    mma16(acc2[im][in_], al[im], bh[in_]);
                }
        }

        if (j+1 < NC) sts_chunk(smem + ((j+1)&1)*BUFFH);
        __syncthreads();
    }

    // epilogue: acc1 + acc2/2048
    const float sc = 1.f/2048.f;
    #pragma unroll
    for (int im=0; im<4; im++){
        int r0 = bm + wm*64 + im*16 + g;
        #pragma unroll
        for (int in_=0; in_<4; in_++){
            int cc = bn + wn*32 + in_*8 + (t<<1);
            if (cc < Nrows){
                float2 v0 = make_float2(fmaf(acc2[im][in_][0], sc, acc1[im][in_][0]),
                                        fmaf(acc2[im][in_][1], sc, acc1[im][in_][1]));
                float2 v1 = make_float2(fmaf(acc2[im][in_][2], sc, acc1[im][in_][2]),
                                        fmaf(acc2[im][in_][3], sc, acc1[im][in_][3]));
                if (MODE==1){
                    float2 r = *(const float2*)&aux[(size_t)r0*ldc + cc];
                    v0.x += r.x; v0.y += r.y;
                    float2 s = *(const float2*)&aux[(size_t)(r0+8)*ldc + cc];
                    v1.x += s.x; v1.y += s.y;
                } else if (MODE==3){
                    float2 b = *(const float2*)&aux[cc];
                    v0.x = softplus_f(v0.x + b.x); v0.y = softplus_f(v0.y + b.y);
                    v1.x = softplus_f(v1.x + b.x); v1.y = softplus_f(v1.y + b.y);
                }
                *(float2*)&C[(size_t)r0*ldc + cc]     = v0;
                *(float2*)&C[(size_t)(r0+8)*ldc + cc] = v1;
            }
        }
    }
}

// ---------------- patch embed: implicit-im2col fp16-split GEMM + bias -------
__global__ void __launch_bounds__(256) mma_patch(
        const float* __restrict__ X,
        const float* __restrict__ W,
        const float* __restrict__ bias,
        float* __restrict__ C)
{
    const int Kd = KPATCH, Nrows = DMODEL, ldc = DMODEL;
    extern __shared__ __half smem[];
    const int tid = threadIdx.x;
    const int wid = tid >> 5, lane = tid & 31;
    const int wm = wid & 1, wn = wid >> 1;
    const int g = lane >> 2, t = lane & 3;
    const int bm = blockIdx.y << 7, bn = blockIdx.x << 7;
    const int NC = (Kd + KCH - 1) / KCH;   // 19

    float acc1[4][4][4], acc2[4][4][4];
    #pragma unroll
    for (int i=0;i<4;i++)
        #pragma unroll
        for (int j=0;j<4;j++)
            #pragma unroll
            for (int q=0;q<4;q++){ acc1[i][j][q]=0.f; acc2[i][j][q]=0.f; }

    float4 regA[4], regB[4];

    auto ldg_chunk = [&](int k0){
        #pragma unroll
        for (int i=0;i<4;i++){
            int e = tid + (i<<8);
            int r = e >> 3, c4 = e & 7;
            int gk0 = k0 + (c4<<2);
            {
                int gm = bm + r;
                int b  = gm >> 8, l = gm & 255;
                int py = l >> 4, px = l & 15;
                const float* xb = X + (size_t)b*3*224*224 + (py*14)*224 + px*14;
                float4 v = make_float4(0.f,0.f,0.f,0.f);
                float* pv = &v.x;
                #pragma unroll
                for (int q=0;q<4;q++){
                    int gk = gk0 + q;
                    if (gk < KPATCH){
                        int cc  = gk / 196;
                        int rem = gk - cc*196;
                        int ky  = rem / 14;
                        int kx  = rem - ky*14;
                        pv[q] = xb[(size_t)cc*50176 + ky*224 + kx];
                    }
                }
                regA[i] = v;
            }
            {
                float4 v = make_float4(0.f,0.f,0.f,0.f);
                int gr = bn + r;
                if (gr < Nrows){
                    const float* p = W + (size_t)gr*Kd + gk0;
                    float* pv = &v.x;
                    if (gk0 + 4 <= Kd) v = *(const float4*)p;
                    else {
                        #pragma unroll
                        for (int q=0;q<4;q++) if (gk0+q < Kd) pv[q] = p[q];
                    }
                }
                regB[i] = v;
            }
        }
    };
    auto sts_chunk = [&](__half* buf){
        #pragma unroll
        for (int i=0;i<4;i++){
            int e = tid + (i<<8);
            int r = e >> 3, c4 = e & 7;
            int off = r*HSTR + (c4<<2);
            split_store4(buf,          buf + SUBT,   off, regA[i]);
            split_store4(buf + 2*SUBT, buf + 3*SUBT, off, regB[i]);
        }
    };

    ldg_chunk(0);
    sts_chunk(smem);
    __syncthreads();

    for (int j=0;j<NC;j++){
        const __half* Ah = smem + (j&1)*BUFFH;
        const __half* Al = Ah + SUBT;
        const __half* Bh = Ah + 2*SUBT;
        const __half* Bl = Ah + 3*SUBT;
        if (j+1 < NC) ldg_chunk((j+1)*KCH);

        #pragma unroll
        for (int ks=0; ks<2; ks++){
            const int k0 = ks*16;
            uint32_t ah[4][4], al[4][4];
            #pragma unroll
            for (int im=0; im<4; im++){
                int rb = (wm*64 + im*16 + g)*HSTR + k0 + 2*t;
                ah[im][0] = *(const uint32_t*)&Ah[rb];
                ah[im][1] = *(const uint32_t*)&Ah[rb + 8*HSTR];
                ah[im][2] = *(const uint32_t*)&Ah[rb + 8];
                ah[im][3] = *(const uint32_t*)&Ah[rb + 8*HSTR + 8];
                al[im][0] = *(const uint32_t*)&Al[rb];
                al[im][1] = *(const uint32_t*)&Al[rb + 8*HSTR];
                al[im][2] = *(const uint32_t*)&Al[rb + 8];
                al[im][3] = *(const uint32_t*)&Al[rb + 8*HSTR + 8];
            }
            uint32_t bh[4][2], bl[4][2];
            #pragma unroll
            for (int in_=0; in_<4; in_++){
                int nb = (wn*32 + in_*8 + g)*HSTR + k0 + 2*t;
                bh[in_][0] = *(const uint32_t*)&Bh[nb];
                bh[in_][1] = *(const uint32_t*)&Bh[nb + 8];
                bl[in_][0] = *(const uint32_t*)&Bl[nb];
                bl[in_][1] = *(const uint32_t*)&Bl[nb + 8];
            }
            #pragma unroll
            for (int im=0; im<4; im++)
                #pragma unroll
                for (int in_=0; in_<4; in_++){
                    mma16(acc1[im][in_], ah[im], bh[in_]);
                    mma16(acc2[im][in_], ah[im], bl[in_]);
                    mma16(acc2[im][in_], al[im], bh[in_]);
                }
        }

        if (j+1 < NC) sts_chunk(smem + ((j+1)&1)*BUFFH);
        __syncthreads();
    }

    const float sc = 1.f/2048.f;
    #pragma unroll
    for (int im=0; im<4; im++){
        int r0 = bm + wm*64 + im*16 + g;
        #pragma unroll
        for (int in_=0; in_<4; in_++){
            int cc = bn + wn*32 + in_*8 + (t<<1);
            if (cc < Nrows){
                float2 b = *(const float2*)&bias[cc];
                float2 v0 = make_float2(fmaf(acc2[im][in_][0], sc, acc1[im][in_][0]) + b.x,
                                        fmaf(acc2[im][in_][1], sc, acc1[im][in_][1]) + b.y);
                float2 v1 = make_float2(fmaf(acc2[im][in_][2], sc, acc1[im][in_][2]) + b.x,
                                        fmaf(acc2[im][in_][3], sc, acc1[im][in_][3]) + b.y);
                *(float2*)&C[(size_t)r0*ldc + cc]     = v0;
                *(float2*)&C[(size_t)(r0+8)*ldc + cc] = v1;
            }
        }
    }
}

// ---------------- LayerNorm over last dim (width 384), warp per row --------
__global__ void layernorm_k(const float* __restrict__ x,
                            const float* __restrict__ w,
                            const float* __restrict__ b,
                            float* __restrict__ out)
{
    int row  = blockIdx.x*8 + (threadIdx.x >> 5);
    int lane = threadIdx.x & 31;
    const float* xr = x + (size_t)row*DMODEL;
    float v[12]; float s=0.f, sq=0.f;
    #pragma unroll
    for (int i=0;i<12;i++){
        float t = xr[lane + i*32];
        v[i] = t; s += t; sq += t*t;
    }
    #pragma unroll
    for (int o=16;o;o>>=1){
        s  += __shfl_xor_sync(0xffffffffu, s,  o);
        sq += __shfl_xor_sync(0xffffffffu, sq, o);
    }
    float m   = s  * (1.f/DMODEL);
    float var = sq * (1.f/DMODEL) - m*m;
    float r   = rsqrtf(var + 1e-5f);
    float* orow = out + (size_t)row*DMODEL;
    #pragma unroll
    for (int i=0;i<12;i++){
        int c = lane + i*32;
        orow[c] = (v[i]-m)*r*w[c] + b[c];
    }
}

// ---------------- causal depthwise conv1d (K=4) + bias + silu --------------
__global__ void conv_silu_k(const float* __restrict__ xz,
                            const float* __restrict__ cw,
                            const float* __restrict__ cb,
                            float* __restrict__ xb)
{
    int idx = blockIdx.x*blockDim.x + threadIdx.x;
    if (idx >= MROWS*DIN) return;
    int d  = idx % DIN;
    int bl = idx / DIN;
    int l  = bl & 255;
    int b  = bl >> 8;
    float acc = cb[d];
    #pragma unroll
    for (int j=0;j<4;j++){
        int ls = l - 3 + j;
        if (ls >= 0)
            acc = fmaf(xz[(size_t)(b*LSEQ+ls)*(2*DIN) + d], cw[d*4+j], acc);
    }
    xb[idx] = silu_f(acc);
}

// ---------------- selective scan: thread per (b,d,n) -----------------------
__global__ void scan_k(const float* __restrict__ dtp,
                       const float* __restrict__ xbp,
                       const float* __restrict__ proj,
                       const float* __restrict__ xz,
                       const float* __restrict__ A_log,
                       const float* __restrict__ Dp,
                       float* __restrict__ y)
{
    int n = threadIdx.x & 15;
    int d = blockIdx.x*16 + (threadIdx.x >> 4);
    int b = blockIdx.y;
    float An = -__expf(A_log[d*NST + n]);
    float Dd = Dp[d];
    float h  = 0.f;
    size_t base = (size_t)b*LSEQ;
    for (int l=0;l<LSEQ;l++){
        size_t row = base + l;
        float dt = dtp[row*DIN + d];
        float xv = xbp[row*DIN + d];
        float Bv = proj[row*PROJW + RLOW + n];
        float Cv = proj[row*PROJW + RLOW + NST + n];
        h = fmaf(h, __expf(dt*An), dt*xv*Bv);
        float p = h*Cv;
        p += __shfl_xor_sync(0xffffffffu, p, 8);
        p += __shfl_xor_sync(0xffffffffu, p, 4);
        p += __shfl_xor_sync(0xffffffffu, p, 2);
        p += __shfl_xor_sync(0xffffffffu, p, 1);
        if (n == 0){
            float z = xz[row*(2*DIN) + DIN + d];
            y[row*DIN + d] = (p + xv*Dd) * silu_f(z);
        }
    }
}

// ---------------- mean-pool over L ------------------------------------------
__global__ void pool_k(const float* __restrict__ ln, float* __restrict__ out)
{
    int b = blockIdx.x;
    int d = threadIdx.x;
    float s = 0.f;
    for (int l=0;l<LSEQ;l++)
        s += ln[(size_t)(b*LSEQ+l)*DMODEL + d];
    out[b*DMODEL + d] = s * (1.f/LSEQ);
}

// ---------------- classifier head -------------------------------------------
__global__ void classifier_k(const float* __restrict__ pool,
                             const float* __restrict__ w,
                             const float* __restrict__ bias,
                             float* __restrict__ out)
{
    int idx = blockIdx.x*blockDim.x + threadIdx.x;
    if (idx >= NCLS*BATCH) return;
    int b = idx & 31;
    int n = idx >> 5;
    const float* pr = pool + b*DMODEL;
    const float* wr = w + (size_t)n*DMODEL;
    float acc = bias[n];
    #pragma unroll 4
    for (int k=0;k<DMODEL;k++)
        acc = fmaf(pr[k], wr[k], acc);
    out[b*NCLS + n] = acc;
}

// ---------------- launch -----------------------------------------------------
extern "C" void kernel_launch(void* const* d_in, const int* in_sizes, int n_in,
                              void* d_out, int out_size)
{
    const float* x         = (const float*)d_in[0];
    const float* patch_w   = (const float*)d_in[1];
    const float* patch_b   = (const float*)d_in[2];
    const float* norm_w    = (const float*)d_in[3];
    const float* norm_b    = (const float*)d_in[4];
    const float* in_proj_w = (const float*)d_in[5];
    const float* conv_w    = (const float*)d_in[6];
    const float* conv_b    = (const float*)d_in[7];
    const float* A_log     = (const float*)d_in[8];
    const float* D_ssm     = (const float*)d_in[9];
    const float* xproj_w   = (const float*)d_in[10];
    const float* dtproj_w  = (const float*)d_in[11];
    const float* dtproj_b  = (const float*)d_in[12];
    const float* out_proj_w= (const float*)d_in[13];
    const float* fnorm_w   = (const float*)d_in[14];
    const float* fnorm_b   = (const float*)d_in[15];
    const float* cls_w     = (const float*)d_in[16];
    const float* cls_b     = (const float*)d_in[17];
    float* out = (float*)d_out;

    float *t, *xn, *xz, *xb, *proj, *dt, *y, *pool;
    cudaGetSymbolAddress((void**)&t,    g_t);
    cudaGetSymbolAddress((void**)&xn,   g_xn);
    cudaGetSymbolAddress((void**)&xz,   g_xz);
    cudaGetSymbolAddress((void**)&xb,   g_xb);
    cudaGetSymbolAddress((void**)&proj, g_proj);
    cudaGetSymbolAddress((void**)&dt,   g_dt);
    cudaGetSymbolAddress((void**)&y,    g_y);
    cudaGetSymbolAddress((void**)&pool, g_pool);

    cudaFuncSetAttribute((const void*)mma_patch,   cudaFuncAttributeMaxDynamicSharedMemorySize, SMEM_BYTES);
    cudaFuncSetAttribute((const void*)mma_gemm<0>, cudaFuncAttributeMaxDynamicSharedMemorySize, SMEM_BYTES);
    cudaFuncSetAttribute((const void*)mma_gemm<1>, cudaFuncAttributeMaxDynamicSharedMemorySize, SMEM_BYTES);
    cudaFuncSetAttribute((const void*)mma_gemm<3>, cudaFuncAttributeMaxDynamicSharedMemorySize, SMEM_BYTES);

    // patch embed -> t : (8192, 384)
    mma_patch<<<dim3(3,64), 256, SMEM_BYTES>>>(x, patch_w, patch_b, t);

    for (int l=0; l<NLAYER; l++){
        layernorm_k<<<1024, 256>>>(t, norm_w + l*DMODEL, norm_b + l*DMODEL, xn);
        // in_proj: (8192,1536) = xn(8192,384) @ W(1536,384)^T
        mma_gemm<0><<<dim3(12,64), 256, SMEM_BYTES>>>(xn, DMODEL,
            in_proj_w + (size_t)l*2*DIN*DMODEL, 2*DIN,
            xz, 2*DIN, DMODEL, nullptr);
        conv_silu_k<<<(MROWS*DIN + 255)/256, 256>>>(xz,
            conv_w + (size_t)l*DIN*4, conv_b + l*DIN, xb);
        // x_proj: (8192,80) = xb(8192,768) @ W(80,768)^T
        mma_gemm<0><<<dim3(1,64), 256, SMEM_BYTES>>>(xb, DIN,
            xproj_w + (size_t)l*PROJW*DIN, PROJW,
            proj, PROJW, DIN, nullptr);
        // dt_proj + softplus: (8192,768) = proj[:, :48](lda=80) @ W(768,48)^T + b
        mma_gemm<3><<<dim3(6,64), 256, SMEM_BYTES>>>(proj, PROJW,
            dtproj_w + (size_t)l*DIN*RLOW, DIN,
            dt, DIN, RLOW, dtproj_b + l*DIN);
        scan_k<<<dim3(48,32), 256>>>(dt, xb, proj, xz,
            A_log + (size_t)l*DIN*NST, D_ssm + l*DIN, y);
        // out_proj + residual: t = y(8192,768) @ W(384,768)^T + t
        mma_gemm<1><<<dim3(3,64), 256, SMEM_BYTES>>>(y, DIN,
            out_proj_w + (size_t)l*DMODEL*DIN, DMODEL,
            t, DMODEL, DIN, t);
    }

    layernorm_k<<<1024, 256>>>(t, fnorm_w, fnorm_b, xn);
    pool_k<<<BATCH, DMODEL>>>(xn, pool);
    classifier_k<<<(NCLS*BATCH + 255)/256, 256>>>(pool, cls_w, cls_b, out);
}